// round 5
// baseline (speedup 1.0000x reference)
#include <cuda_runtime.h>
#include <cuda_bf16.h>

// LayerNorm over last dim W=256 for (8,128,128,256) fp32 + per-channel affine.
// Software-pipelined persistent warps: each warp handles 8 rows; the next
// row's loads are issued BEFORE the current row's reduction, so the serial
// SHFL/FADD tail overlaps DRAM latency. Outstanding loads/warp stays at 2
// (the R1 sweet spot). Plain evict-normal loads and stores (measured best).

#define EPS 1e-8f
#define W_DIM 256
#define C_DIM 128

__global__ __launch_bounds__(256, 8)
void ln_pipe_kernel(const float* __restrict__ inp,
                    const float* __restrict__ gain,
                    const float* __restrict__ bias,
                    float* __restrict__ out,
                    int n_rows)
{
    const int lane = threadIdx.x & 31;
    const int warp = (blockIdx.x << 3) + (threadIdx.x >> 5);
    const int n_warps = gridDim.x << 3;

    const float4* in4  = reinterpret_cast<const float4*>(inp);
    float4*       out4 = reinterpret_cast<float4*>(out);
    const float inv_w = 1.0f / (float)W_DIM;
    const int lane2 = lane * 2;

    int row = warp;
    if (row >= n_rows) return;

    // Prologue: loads for first row.
    float4 v0 = in4[(size_t)row * 64 + lane2 + 0];
    float4 v1 = in4[(size_t)row * 64 + lane2 + 1];

    for (;;) {
        const int next = row + n_warps;
        const bool has_next = next < n_rows;

        // Issue next row's loads BEFORE the serial reduction of this row.
        float4 w0, w1;
        if (has_next) {
            w0 = in4[(size_t)next * 64 + lane2 + 0];
            w1 = in4[(size_t)next * 64 + lane2 + 1];
        }

        // Affine params for this row (L1-hot after first touch).
        const int c = (row >> 7) & (C_DIM - 1);   // row = ((b*C+c)*H + h)
        const float g = __ldg(gain + c);
        const float b = __ldg(bias + c);

        float s  = ((v0.x + v0.y) + (v0.z + v0.w)) + ((v1.x + v1.y) + (v1.z + v1.w));
        float ss = ((v0.x*v0.x + v0.y*v0.y) + (v0.z*v0.z + v0.w*v0.w))
                 + ((v1.x*v1.x + v1.y*v1.y) + (v1.z*v1.z + v1.w*v1.w));

        #pragma unroll
        for (int off = 16; off > 0; off >>= 1) {
            s  += __shfl_xor_sync(0xFFFFFFFFu, s,  off);
            ss += __shfl_xor_sync(0xFFFFFFFFu, ss, off);
        }

        float mean = s * inv_w;
        float var  = ss * inv_w - mean * mean;
        float rstd = rsqrtf(var + EPS);
        float scale = rstd * g;
        float shift = b - mean * scale;

        v0.x = v0.x * scale + shift;  v0.y = v0.y * scale + shift;
        v0.z = v0.z * scale + shift;  v0.w = v0.w * scale + shift;
        v1.x = v1.x * scale + shift;  v1.y = v1.y * scale + shift;
        v1.z = v1.z * scale + shift;  v1.w = v1.w * scale + shift;

        out4[(size_t)row * 64 + lane2 + 0] = v0;
        out4[(size_t)row * 64 + lane2 + 1] = v1;

        if (!has_next) break;
        row = next;
        v0 = w0;
        v1 = w1;
    }
}

extern "C" void kernel_launch(void* const* d_in, const int* in_sizes, int n_in,
                              void* d_out, int out_size) {
    const float* inp  = (const float*)d_in[0];
    const float* gain = (const float*)d_in[1];
    const float* bias = (const float*)d_in[2];
    float* out = (float*)d_out;

    int n_rows = in_sizes[0] / W_DIM;   // 131072
    // 2048 blocks * 8 warps = 16384 warps -> exactly 8 rows per warp.
    int blocks = 2048;

    ln_pipe_kernel<<<blocks, 256>>>(inp, gain, bias, out, n_rows);
}

// round 6
// speedup vs baseline: 1.0713x; 1.0713x over previous
#include <cuda_runtime.h>
#include <cuda_bf16.h>

// LayerNorm over last dim W=256 for (8,128,128,256) fp32 + per-channel affine.
// R1 shape (1 warp/row, 2x LDG.128, shuffle reduce, plain loads/stores) with
// ONE change: fully-coalesced lane layout. v0 = in4[lane], v1 = in4[lane+32]
// -> each LDG.128/STG.128 covers a contiguous 512B (full sectors, full lines),
// instead of the half-sector interleave of lane*2 / lane*2+1.

#define EPS 1e-8f
#define W_DIM 256
#define C_DIM 128

__global__ __launch_bounds__(256, 8)
void ln_coal_kernel(const float* __restrict__ inp,
                    const float* __restrict__ gain,
                    const float* __restrict__ bias,
                    float* __restrict__ out,
                    int n_rows)
{
    const int warp_in_block = threadIdx.x >> 5;
    const int lane = threadIdx.x & 31;
    const int row = blockIdx.x * 8 + warp_in_block;
    if (row >= n_rows) return;

    // Affine params first: independent loads, overlap the bulk-load latency.
    const int c = (row >> 7) & (C_DIM - 1);   // row = ((b*C+c)*H + h), H=128
    const float g = __ldg(gain + c);
    const float b = __ldg(bias + c);

    const float4* in4 = reinterpret_cast<const float4*>(inp) + (size_t)row * 64;
    float4*      out4 = reinterpret_cast<float4*>(out)       + (size_t)row * 64;

    // Coalesced: instruction 0 covers float4s [0,32) (bytes 0..511),
    // instruction 1 covers float4s [32,64) (bytes 512..1023).
    float4 v0 = in4[lane];
    float4 v1 = in4[lane + 32];

    float s  = ((v0.x + v0.y) + (v0.z + v0.w)) + ((v1.x + v1.y) + (v1.z + v1.w));
    float ss = ((v0.x*v0.x + v0.y*v0.y) + (v0.z*v0.z + v0.w*v0.w))
             + ((v1.x*v1.x + v1.y*v1.y) + (v1.z*v1.z + v1.w*v1.w));

    #pragma unroll
    for (int off = 16; off > 0; off >>= 1) {
        s  += __shfl_xor_sync(0xFFFFFFFFu, s,  off);
        ss += __shfl_xor_sync(0xFFFFFFFFu, ss, off);
    }

    const float inv_w = 1.0f / (float)W_DIM;
    float mean = s * inv_w;
    float var  = ss * inv_w - mean * mean;
    float rstd = rsqrtf(var + EPS);

    float scale = rstd * g;
    float shift = b - mean * scale;

    v0.x = v0.x * scale + shift;  v0.y = v0.y * scale + shift;
    v0.z = v0.z * scale + shift;  v0.w = v0.w * scale + shift;
    v1.x = v1.x * scale + shift;  v1.y = v1.y * scale + shift;
    v1.z = v1.z * scale + shift;  v1.w = v1.w * scale + shift;

    out4[lane]      = v0;
    out4[lane + 32] = v1;
}

extern "C" void kernel_launch(void* const* d_in, const int* in_sizes, int n_in,
                              void* d_out, int out_size) {
    const float* inp  = (const float*)d_in[0];
    const float* gain = (const float*)d_in[1];
    const float* bias = (const float*)d_in[2];
    float* out = (float*)d_out;

    int n_rows = in_sizes[0] / W_DIM;   // 131072
    int blocks = (n_rows + 7) / 8;      // 16384

    ln_coal_kernel<<<blocks, 256>>>(inp, gain, bias, out, n_rows);
}